// round 10
// baseline (speedup 1.0000x reference)
#include <cuda_runtime.h>
#include <cuda_fp16.h>

// Problem constants (fixed by the dataset)
#define NN 50000
#define LL 4
#define EE 1600000
#define CC 128
#define NM 8          // m<4 -> phi_inverse[l], m>=4 -> phi[l-4]
#define CAP 72        // fixed row-bin capacity (Poisson(32): P(>72) ~ 5e-10/row)
#define MAXSPILL 4096

#define GEMM_R 16

// ----------------------------------------------------------------------------
// Scratch (static device globals; allocation-free per harness rules)
// ----------------------------------------------------------------------------
__device__ int   g_cnt[NM][NN];                              // row counts / cursors
__device__ __align__(16) int2 g_edge[(size_t)NM * NN * CAP]; // row bins: {col, val bits}
__device__ int   g_nspill;
__device__ int4  g_spill[MAXSPILL];                          // {m, r, c, val bits}
__device__ __align__(16) __half g_Y1[(size_t)LL * NN * CC];  // feats @ W (fp16)
__device__ __align__(16) __half g_Y2[(size_t)LL * NN * CC];  // theta*(phi_inv@Y1) (fp16)

// packed dual fp32 FMA: d.lo += a.lo*b.lo ; d.hi += a.hi*b.hi
__device__ __forceinline__ void ffma2(unsigned long long& d,
                                      unsigned long long a,
                                      unsigned long long b) {
    asm("fma.rn.f32x2 %0, %1, %2, %0;" : "+l"(d) : "l"(a), "l"(b));
}

// ----------------------------------------------------------------------------
// 1) zero counters + spill count
// ----------------------------------------------------------------------------
__global__ void zero_cnt_kernel() {
    int i = blockIdx.x * blockDim.x + threadIdx.x;
    if (i < NM * NN) ((int*)g_cnt)[i] = 0;
    if (i == 0) g_nspill = 0;
}

// ----------------------------------------------------------------------------
// 2) scatter edges directly into fixed-capacity row bins
//    4 edges/thread via int4/float4; grid (EE/512, NM), 128 threads
// ----------------------------------------------------------------------------
__global__ void __launch_bounds__(128) scatter_kernel(
    const int* __restrict__ phi_idx, const float* __restrict__ phi_val,
    const int* __restrict__ inv_idx, const float* __restrict__ inv_val) {
    int m = blockIdx.y;
    const int*   base = (m < LL) ? (inv_idx + (size_t)m * 2 * EE)
                                 : (phi_idx + (size_t)(m - LL) * 2 * EE);
    const float* vals = (m < LL) ? (inv_val + (size_t)m * EE)
                                 : (phi_val + (size_t)(m - LL) * EE);
    int e = blockIdx.x * 512 + threadIdx.x * 4;
    int4   r4 = *(const int4*)(base + e);
    int4   c4 = *(const int4*)(base + EE + e);
    float4 v4 = *(const float4*)(vals + e);

    int rr[4] = {r4.x, r4.y, r4.z, r4.w};
    int cc[4] = {c4.x, c4.y, c4.z, c4.w};
    float vv[4] = {v4.x, v4.y, v4.z, v4.w};
    #pragma unroll
    for (int j = 0; j < 4; j++) {
        int pos = atomicAdd(&g_cnt[m][rr[j]], 1);
        if (pos < CAP) {
            g_edge[((size_t)m * NN + rr[j]) * CAP + pos] =
                make_int2(cc[j], __float_as_int(vv[j]));
        } else {
            int s = atomicAdd(&g_nspill, 1);
            if (s < MAXSPILL)
                g_spill[s] = make_int4(m, rr[j], cc[j], __float_as_int(vv[j]));
        }
    }
}

// ----------------------------------------------------------------------------
// 3) GEMM: Y1 = feats @ W (fp16 out), FFMA2 mainloop, 16 rows/block
// ----------------------------------------------------------------------------
__global__ void __launch_bounds__(128) gemm_kernel(const float* __restrict__ feats,
                                                   const float* __restrict__ W) {
    __shared__ __align__(16) float Ws[CC * 66];      // W half, transposed [c][k], pad 66
    __shared__ __align__(16) float Fs[GEMM_R * CC];  // feature tile [rr][k]
    int tid = threadIdx.x;           // output column c
    int row0 = blockIdx.x * GEMM_R;  // t = l*NN + n

    #pragma unroll
    for (int rr = 0; rr < GEMM_R; rr++) {
        int t = row0 + rr;
        int l = t / NN;
        int n = t - l * NN;
        Fs[rr * CC + tid] = feats[((size_t)n * LL + l) * CC + tid];
    }

    unsigned long long acc[GEMM_R];
    #pragma unroll
    for (int rr = 0; rr < GEMM_R; rr++) acc[rr] = 0ull;

    for (int h = 0; h < 2; h++) {
        __syncthreads();
        #pragma unroll
        for (int i = tid; i < 64 * CC; i += 128) {
            int k = i >> 7;
            int c = i & 127;
            Ws[c * 66 + k] = W[(size_t)(h * 64 + k) * CC + c];
        }
        __syncthreads();

        #pragma unroll
        for (int k = 0; k < 64; k += 4) {
            unsigned long long w01 = *(const unsigned long long*)&Ws[tid * 66 + k];
            unsigned long long w23 = *(const unsigned long long*)&Ws[tid * 66 + k + 2];
            #pragma unroll
            for (int rr = 0; rr < GEMM_R; rr++) {
                ulonglong2 f = *(const ulonglong2*)&Fs[rr * CC + h * 64 + k];
                ffma2(acc[rr], f.x, w01);
                ffma2(acc[rr], f.y, w23);
            }
        }
    }

    #pragma unroll
    for (int rr = 0; rr < GEMM_R; rr++) {
        float lo, hi;
        asm("mov.b64 {%0,%1}, %2;" : "=f"(lo), "=f"(hi) : "l"(acc[rr]));
        float s = lo + hi;
        int t = row0 + rr;
        int l = t / NN;
        int n = t - l * NN;
        g_Y1[(size_t)l * NN * CC + (size_t)n * CC + tid] = __float2half_rn(s);
    }
}

// ----------------------------------------------------------------------------
// SpMM edge-pair inner step (shared by both stages)
// ----------------------------------------------------------------------------
__device__ __forceinline__ void edge_accum(const uint2* __restrict__ Xv, int col,
                                           float val, int lane, float4& acc) {
    uint2 xw = __ldg(&Xv[col * 32 + lane]);
    float2 fa = __half22float2(*(const half2*)&xw.x);
    float2 fb = __half22float2(*(const half2*)&xw.y);
    acc.x = fmaf(val, fa.x, acc.x);
    acc.y = fmaf(val, fa.y, acc.y);
    acc.z = fmaf(val, fb.x, acc.z);
    acc.w = fmaf(val, fb.y, acc.w);
}

// ----------------------------------------------------------------------------
// 4) SpMM stage 1: Y2[l] = theta .* (phi_inv[l] @ Y1[l])
//    warp/row; paired-record broadcast LDG.128, scalar tail
// ----------------------------------------------------------------------------
__global__ void __launch_bounds__(256) spmm_inv_kernel(const float* __restrict__ theta) {
    int wg   = (blockIdx.x * blockDim.x + threadIdx.x) >> 5;
    int lane = threadIdx.x & 31;
    int l = wg / NN;
    int r = wg - l * NN;
    int cnt = min(__ldg(&g_cnt[l][r]), CAP);
    const uint2* Xv = (const uint2*)(g_Y1 + (size_t)l * NN * CC);
    const int4* bin4 = (const int4*)(g_edge + ((size_t)l * NN + r) * CAP);

    float4 acc = make_float4(0.f, 0.f, 0.f, 0.f);
    int npair = cnt >> 1;
    #pragma unroll 2
    for (int p = 0; p < npair; p++) {
        int4 rp = __ldg(&bin4[p]);                // two records, one broadcast load
        edge_accum(Xv, rp.x, __int_as_float(rp.y), lane, acc);
        edge_accum(Xv, rp.z, __int_as_float(rp.w), lane, acc);
    }
    if (cnt & 1) {
        int2 rec = __ldg(&((const int2*)bin4)[cnt - 1]);
        edge_accum(Xv, rec.x, __int_as_float(rec.y), lane, acc);
    }
    float t = __ldg(&theta[r]);
    half2 h0 = __floats2half2_rn(acc.x * t, acc.y * t);
    half2 h1 = __floats2half2_rn(acc.z * t, acc.w * t);
    uint2 o;
    o.x = *(const unsigned int*)&h0;
    o.y = *(const unsigned int*)&h1;
    ((uint2*)(g_Y2 + (size_t)l * NN * CC))[r * 32 + lane] = o;
}

// ----------------------------------------------------------------------------
// 4b) spill fix-up for stage 1 (normally 0 iterations)
// ----------------------------------------------------------------------------
__global__ void spill_fix1_kernel(const float* __restrict__ theta) {
    int n = min(g_nspill, MAXSPILL);
    int tid = threadIdx.x;
    for (int i = 0; i < n; i++) {
        int4 s = g_spill[i];
        if (s.x >= LL) continue;                  // stage-1 handles m<4 only
        int l = s.x, r = s.y, c = s.z;
        float v = __int_as_float(s.w) * theta[r];
        if (tid < 64) {
            const half2* y1 = (const half2*)(g_Y1 + (size_t)l * NN * CC);
            half2* y2 = (half2*)(g_Y2 + (size_t)l * NN * CC);
            float2 x = __half22float2(y1[(size_t)c * 64 + tid]);
            atomicAdd(&y2[(size_t)r * 64 + tid], __floats2half2_rn(v * x.x, v * x.y));
        }
    }
}

// ----------------------------------------------------------------------------
// 5) SpMM stage 2: out[n][l][:] = phi[l] @ Y2[l]   (fp32 output)
// ----------------------------------------------------------------------------
__global__ void __launch_bounds__(256) spmm_phi_kernel(float* __restrict__ outp) {
    int wg   = (blockIdx.x * blockDim.x + threadIdx.x) >> 5;
    int lane = threadIdx.x & 31;
    int l = wg / NN;
    int r = wg - l * NN;
    int m = LL + l;
    int cnt = min(__ldg(&g_cnt[m][r]), CAP);
    const uint2* Xv = (const uint2*)(g_Y2 + (size_t)l * NN * CC);
    const int4* bin4 = (const int4*)(g_edge + ((size_t)m * NN + r) * CAP);

    float4 acc = make_float4(0.f, 0.f, 0.f, 0.f);
    int npair = cnt >> 1;
    #pragma unroll 2
    for (int p = 0; p < npair; p++) {
        int4 rp = __ldg(&bin4[p]);
        edge_accum(Xv, rp.x, __int_as_float(rp.y), lane, acc);
        edge_accum(Xv, rp.z, __int_as_float(rp.w), lane, acc);
    }
    if (cnt & 1) {
        int2 rec = __ldg(&((const int2*)bin4)[cnt - 1]);
        edge_accum(Xv, rec.x, __int_as_float(rec.y), lane, acc);
    }
    ((float4*)outp)[(r * LL + l) * 32 + lane] = acc;   // [n][l][c]
}

// ----------------------------------------------------------------------------
// 5b) spill fix-up for stage 2 (normally 0 iterations)
// ----------------------------------------------------------------------------
__global__ void spill_fix2_kernel(float* __restrict__ outp) {
    int n = min(g_nspill, MAXSPILL);
    int tid = threadIdx.x;
    for (int i = 0; i < n; i++) {
        int4 s = g_spill[i];
        if (s.x < LL) continue;                   // stage-2 handles m>=4 only
        int l = s.x - LL, r = s.y, c = s.z;
        float v = __int_as_float(s.w);
        const half2* y2 = (const half2*)(g_Y2 + (size_t)l * NN * CC);
        float2 x = __half22float2(y2[(size_t)c * 64 + (tid >> 1)]);
        float xv = (tid & 1) ? x.y : x.x;
        atomicAdd(&outp[((size_t)r * LL + l) * CC + tid], v * xv);
    }
}

// ----------------------------------------------------------------------------
// launch: minimal fork-join
//   s1: zero -> scatter -[evS]
//   s0: gemm --- wait(evS) -> spmm_inv -> spill1 -> spmm_phi -> spill2
// ----------------------------------------------------------------------------
extern "C" void kernel_launch(void* const* d_in, const int* in_sizes, int n_in,
                              void* d_out, int out_size) {
    const int*   phi_idx = (const int*)d_in[0];    // [L,2,E]
    const float* phi_val = (const float*)d_in[1];  // [L,E]
    const int*   inv_idx = (const int*)d_in[2];    // [L,2,E]
    const float* inv_val = (const float*)d_in[3];  // [L,E]
    const float* feats   = (const float*)d_in[4];  // [N,L,C]
    const float* W       = (const float*)d_in[5];  // [C,C]
    const float* theta   = (const float*)d_in[6];  // [N]
    float*       outp    = (float*)d_out;          // [N,L,C]

    static cudaStream_t s1 = nullptr;
    static cudaEvent_t evRoot = nullptr, evS = nullptr;
    if (s1 == nullptr) {
        cudaStreamCreateWithFlags(&s1, cudaStreamNonBlocking);
        cudaEventCreateWithFlags(&evRoot, cudaEventDisableTiming);
        cudaEventCreateWithFlags(&evS,    cudaEventDisableTiming);
    }

    // fork
    cudaEventRecord(evRoot, 0);
    cudaStreamWaitEvent(s1, evRoot, 0);

    // CSR-bin build on s1 (latency-bound; SM pipes mostly idle)
    zero_cnt_kernel<<<(NM * NN + 255) / 256, 256, 0, s1>>>();
    dim3 gE(EE / 512, NM);
    scatter_kernel<<<gE, 128, 0, s1>>>(phi_idx, phi_val, inv_idx, inv_val);
    cudaEventRecord(evS, s1);

    // GEMM on capture stream, concurrent with scatter
    gemm_kernel<<<(LL * NN) / GEMM_R, 128>>>(feats, W);

    // join, then SpMM chain
    cudaStreamWaitEvent(0, evS, 0);
    spmm_inv_kernel<<<(LL * NN) / 8, 256>>>(theta);
    spill_fix1_kernel<<<1, 128>>>(theta);
    spmm_phi_kernel<<<(LL * NN) / 8, 256>>>(outp);
    spill_fix2_kernel<<<1, 128>>>(outp);
}

// round 11
// speedup vs baseline: 1.0856x; 1.0856x over previous
#include <cuda_runtime.h>
#include <cuda_fp16.h>

// Problem constants (fixed by the dataset)
#define NN 50000
#define LL 4
#define EE 1600000
#define CC 128
#define NM 8          // m<4 -> phi_inverse[l], m>=4 -> phi[l-4]
#define CAP 72        // fixed row-bin capacity (Poisson(32): P(>72) ~ 5e-10/row)
#define MAXSPILL 4096

#define GEMM_R 16

// ----------------------------------------------------------------------------
// Scratch (static device globals; allocation-free per harness rules)
// ----------------------------------------------------------------------------
__device__ int   g_cnt[NM][NN];                              // row counts / cursors
__device__ __align__(16) int2 g_edge[(size_t)NM * NN * CAP]; // row bins: {col, val bits}
__device__ int   g_nspill;
__device__ int4  g_spill[MAXSPILL];                          // {m, r, c, val bits}
__device__ __align__(16) __half g_Y1[(size_t)LL * NN * CC];  // feats @ W (fp16)
__device__ __align__(16) __half g_Y2[(size_t)LL * NN * CC];  // theta*(phi_inv@Y1) (fp16)

// packed dual fp32 FMA: d.lo += a.lo*b.lo ; d.hi += a.hi*b.hi
__device__ __forceinline__ void ffma2(unsigned long long& d,
                                      unsigned long long a,
                                      unsigned long long b) {
    asm("fma.rn.f32x2 %0, %1, %2, %0;" : "+l"(d) : "l"(a), "l"(b));
}

// ----------------------------------------------------------------------------
// 1) zero counters + spill count
// ----------------------------------------------------------------------------
__global__ void zero_cnt_kernel() {
    int i = blockIdx.x * blockDim.x + threadIdx.x;
    if (i < NM * NN) ((int*)g_cnt)[i] = 0;
    if (i == 0) g_nspill = 0;
}

// ----------------------------------------------------------------------------
// 2) scatter edges directly into fixed-capacity row bins
//    4 edges/thread via int4/float4; grid (EE/512, NM), 128 threads
// ----------------------------------------------------------------------------
__global__ void __launch_bounds__(128) scatter_kernel(
    const int* __restrict__ phi_idx, const float* __restrict__ phi_val,
    const int* __restrict__ inv_idx, const float* __restrict__ inv_val) {
    int m = blockIdx.y;
    const int*   base = (m < LL) ? (inv_idx + (size_t)m * 2 * EE)
                                 : (phi_idx + (size_t)(m - LL) * 2 * EE);
    const float* vals = (m < LL) ? (inv_val + (size_t)m * EE)
                                 : (phi_val + (size_t)(m - LL) * EE);
    int e = blockIdx.x * 512 + threadIdx.x * 4;
    int4   r4 = *(const int4*)(base + e);
    int4   c4 = *(const int4*)(base + EE + e);
    float4 v4 = *(const float4*)(vals + e);

    int rr[4] = {r4.x, r4.y, r4.z, r4.w};
    int cc[4] = {c4.x, c4.y, c4.z, c4.w};
    float vv[4] = {v4.x, v4.y, v4.z, v4.w};
    #pragma unroll
    for (int j = 0; j < 4; j++) {
        int pos = atomicAdd(&g_cnt[m][rr[j]], 1);
        if (pos < CAP) {
            g_edge[((size_t)m * NN + rr[j]) * CAP + pos] =
                make_int2(cc[j], __float_as_int(vv[j]));
        } else {
            int s = atomicAdd(&g_nspill, 1);
            if (s < MAXSPILL)
                g_spill[s] = make_int4(m, rr[j], cc[j], __float_as_int(vv[j]));
        }
    }
}

// ----------------------------------------------------------------------------
// 3) GEMM: Y1 = feats @ W (fp16 out), FFMA2 mainloop, 16 rows/block
// ----------------------------------------------------------------------------
__global__ void __launch_bounds__(128) gemm_kernel(const float* __restrict__ feats,
                                                   const float* __restrict__ W) {
    __shared__ __align__(16) float Ws[CC * 66];      // W half, transposed [c][k], pad 66
    __shared__ __align__(16) float Fs[GEMM_R * CC];  // feature tile [rr][k]
    int tid = threadIdx.x;           // output column c
    int row0 = blockIdx.x * GEMM_R;  // t = l*NN + n

    #pragma unroll
    for (int rr = 0; rr < GEMM_R; rr++) {
        int t = row0 + rr;
        int l = t / NN;
        int n = t - l * NN;
        Fs[rr * CC + tid] = feats[((size_t)n * LL + l) * CC + tid];
    }

    unsigned long long acc[GEMM_R];
    #pragma unroll
    for (int rr = 0; rr < GEMM_R; rr++) acc[rr] = 0ull;

    for (int h = 0; h < 2; h++) {
        __syncthreads();
        #pragma unroll
        for (int i = tid; i < 64 * CC; i += 128) {
            int k = i >> 7;
            int c = i & 127;
            Ws[c * 66 + k] = W[(size_t)(h * 64 + k) * CC + c];
        }
        __syncthreads();

        #pragma unroll
        for (int k = 0; k < 64; k += 4) {
            unsigned long long w01 = *(const unsigned long long*)&Ws[tid * 66 + k];
            unsigned long long w23 = *(const unsigned long long*)&Ws[tid * 66 + k + 2];
            #pragma unroll
            for (int rr = 0; rr < GEMM_R; rr++) {
                ulonglong2 f = *(const ulonglong2*)&Fs[rr * CC + h * 64 + k];
                ffma2(acc[rr], f.x, w01);
                ffma2(acc[rr], f.y, w23);
            }
        }
    }

    #pragma unroll
    for (int rr = 0; rr < GEMM_R; rr++) {
        float lo, hi;
        asm("mov.b64 {%0,%1}, %2;" : "=f"(lo), "=f"(hi) : "l"(acc[rr]));
        float s = lo + hi;
        int t = row0 + rr;
        int l = t / NN;
        int n = t - l * NN;
        g_Y1[(size_t)l * NN * CC + (size_t)n * CC + tid] = __float2half_rn(s);
    }
}

// ----------------------------------------------------------------------------
// 4) SpMM stage 1: Y2[l] = theta .* (phi_inv[l] @ Y1[l])
//    warp/row; independent broadcast int2 loads, unroll 4 (R8 form)
// ----------------------------------------------------------------------------
__global__ void __launch_bounds__(256) spmm_inv_kernel(const float* __restrict__ theta) {
    int wg   = (blockIdx.x * blockDim.x + threadIdx.x) >> 5;
    unsigned lane = threadIdx.x & 31;
    int l = wg / NN;
    int r = wg - l * NN;
    int cnt = min(__ldg(&g_cnt[l][r]), CAP);
    const uint2* Xv = (const uint2*)(g_Y1 + (size_t)l * NN * CC);
    const int2*  bin = g_edge + ((size_t)l * NN + r) * CAP;

    float4 acc = make_float4(0.f, 0.f, 0.f, 0.f);
    #pragma unroll 4
    for (int e = 0; e < cnt; e++) {
        int2 rec = __ldg(&bin[e]);                // uniform across warp -> broadcast
        float val = __int_as_float(rec.y);
        uint2 xw = Xv[((unsigned)rec.x << 5) | lane];   // 32-bit index math
        float2 fa = __half22float2(*(const half2*)&xw.x);
        float2 fb = __half22float2(*(const half2*)&xw.y);
        acc.x = fmaf(val, fa.x, acc.x);
        acc.y = fmaf(val, fa.y, acc.y);
        acc.z = fmaf(val, fb.x, acc.z);
        acc.w = fmaf(val, fb.y, acc.w);
    }
    float t = __ldg(&theta[r]);
    half2 h0 = __floats2half2_rn(acc.x * t, acc.y * t);
    half2 h1 = __floats2half2_rn(acc.z * t, acc.w * t);
    uint2 o;
    o.x = *(const unsigned int*)&h0;
    o.y = *(const unsigned int*)&h1;
    ((uint2*)(g_Y2 + (size_t)l * NN * CC))[((unsigned)r << 5) | lane] = o;
}

// ----------------------------------------------------------------------------
// 4b) spill fix-up for stage 1 (normally 0 iterations)
// ----------------------------------------------------------------------------
__global__ void spill_fix1_kernel(const float* __restrict__ theta) {
    int n = min(g_nspill, MAXSPILL);
    int tid = threadIdx.x;
    for (int i = 0; i < n; i++) {
        int4 s = g_spill[i];
        if (s.x >= LL) continue;                  // stage-1 handles m<4 only
        int l = s.x, r = s.y, c = s.z;
        float v = __int_as_float(s.w) * theta[r];
        if (tid < 64) {
            const half2* y1 = (const half2*)(g_Y1 + (size_t)l * NN * CC);
            half2* y2 = (half2*)(g_Y2 + (size_t)l * NN * CC);
            float2 x = __half22float2(y1[(size_t)c * 64 + tid]);
            atomicAdd(&y2[(size_t)r * 64 + tid], __floats2half2_rn(v * x.x, v * x.y));
        }
    }
}

// ----------------------------------------------------------------------------
// 5) SpMM stage 2: out[n][l][:] = phi[l] @ Y2[l]   (fp32 output, R8 form)
// ----------------------------------------------------------------------------
__global__ void __launch_bounds__(256) spmm_phi_kernel(float* __restrict__ outp) {
    int wg   = (blockIdx.x * blockDim.x + threadIdx.x) >> 5;
    unsigned lane = threadIdx.x & 31;
    int l = wg / NN;
    int r = wg - l * NN;
    int m = LL + l;
    int cnt = min(__ldg(&g_cnt[m][r]), CAP);
    const uint2* Xv = (const uint2*)(g_Y2 + (size_t)l * NN * CC);
    const int2*  bin = g_edge + ((size_t)m * NN + r) * CAP;

    float4 acc = make_float4(0.f, 0.f, 0.f, 0.f);
    #pragma unroll 4
    for (int e = 0; e < cnt; e++) {
        int2 rec = __ldg(&bin[e]);                // uniform across warp -> broadcast
        float val = __int_as_float(rec.y);
        uint2 xw = Xv[((unsigned)rec.x << 5) | lane];   // 32-bit index math
        float2 fa = __half22float2(*(const half2*)&xw.x);
        float2 fb = __half22float2(*(const half2*)&xw.y);
        acc.x = fmaf(val, fa.x, acc.x);
        acc.y = fmaf(val, fa.y, acc.y);
        acc.z = fmaf(val, fb.x, acc.z);
        acc.w = fmaf(val, fb.y, acc.w);
    }
    ((float4*)outp)[((unsigned)(r * LL + l) << 5) | lane] = acc;   // [n][l][c]
}

// ----------------------------------------------------------------------------
// 5b) spill fix-up for stage 2 (normally 0 iterations)
// ----------------------------------------------------------------------------
__global__ void spill_fix2_kernel(float* __restrict__ outp) {
    int n = min(g_nspill, MAXSPILL);
    int tid = threadIdx.x;
    for (int i = 0; i < n; i++) {
        int4 s = g_spill[i];
        if (s.x < LL) continue;                   // stage-2 handles m>=4 only
        int l = s.x - LL, r = s.y, c = s.z;
        float v = __int_as_float(s.w);
        const half2* y2 = (const half2*)(g_Y2 + (size_t)l * NN * CC);
        float2 x = __half22float2(y2[(size_t)c * 64 + (tid >> 1)]);
        float xv = (tid & 1) ? x.y : x.x;
        atomicAdd(&outp[((size_t)r * LL + l) * CC + tid], v * xv);
    }
}

// ----------------------------------------------------------------------------
// launch: minimal fork-join (measured +41us win in R9)
//   s1: zero -> scatter -[evS]
//   s0: gemm --- wait(evS) -> spmm_inv -> spill1 -> spmm_phi -> spill2
// ----------------------------------------------------------------------------
extern "C" void kernel_launch(void* const* d_in, const int* in_sizes, int n_in,
                              void* d_out, int out_size) {
    const int*   phi_idx = (const int*)d_in[0];    // [L,2,E]
    const float* phi_val = (const float*)d_in[1];  // [L,E]
    const int*   inv_idx = (const int*)d_in[2];    // [L,2,E]
    const float* inv_val = (const float*)d_in[3];  // [L,E]
    const float* feats   = (const float*)d_in[4];  // [N,L,C]
    const float* W       = (const float*)d_in[5];  // [C,C]
    const float* theta   = (const float*)d_in[6];  // [N]
    float*       outp    = (float*)d_out;          // [N,L,C]

    static cudaStream_t s1 = nullptr;
    static cudaEvent_t evRoot = nullptr, evS = nullptr;
    if (s1 == nullptr) {
        cudaStreamCreateWithFlags(&s1, cudaStreamNonBlocking);
        cudaEventCreateWithFlags(&evRoot, cudaEventDisableTiming);
        cudaEventCreateWithFlags(&evS,    cudaEventDisableTiming);
    }

    // fork
    cudaEventRecord(evRoot, 0);
    cudaStreamWaitEvent(s1, evRoot, 0);

    // bin build on s1 (latency-bound; SM pipes mostly idle)
    zero_cnt_kernel<<<(NM * NN + 255) / 256, 256, 0, s1>>>();
    dim3 gE(EE / 512, NM);
    scatter_kernel<<<gE, 128, 0, s1>>>(phi_idx, phi_val, inv_idx, inv_val);
    cudaEventRecord(evS, s1);

    // GEMM on capture stream, concurrent with scatter
    gemm_kernel<<<(LL * NN) / GEMM_R, 128>>>(feats, W);

    // join, then SpMM chain
    cudaStreamWaitEvent(0, evS, 0);
    spmm_inv_kernel<<<(LL * NN) / 8, 256>>>(theta);
    spill_fix1_kernel<<<1, 128>>>(theta);
    spmm_phi_kernel<<<(LL * NN) / 8, 256>>>(outp);
    spill_fix2_kernel<<<1, 128>>>(outp);
}